// round 14
// baseline (speedup 1.0000x reference)
#include <cuda_runtime.h>
#include <cuda_bf16.h>
#include <cuda_fp16.h>
#include <cstdint>

#define NN 50000
#define EE 800000
#define FD 128
#define ZD 64
#define CAP 128          // bucket capacity per node (Poisson(16); overflow ~1e-18)

static constexpr int GB = (NN + 127) / 128;          // 391 GEMM tiles
static constexpr int EB = (EE + 255) / 256;          // 3125 edge blocks

// ---------------- scratch (device globals; no allocation allowed) ----------
__device__ __align__(256) float  g_bufA[NN * FD];    // aliased: fp16 A rows
__device__ __align__(256) __half g_H16[NN * FD];
__device__ __align__(256) __half g_Bf16[128 * 512 + 2 * 128 * 128];
__device__ __align__(256) int    g_src[NN * CAP];
__device__ __align__(256) uint2  g_sw[NN * CAP];     // packed {s<<8, w}, padded to 8
__device__ int   g_cnt[NN];
__device__ int   g_is64;

// ---------------- PTX helpers ----------------------------------------------
__device__ __forceinline__ uint32_t smem_u32(const void* p) {
    uint32_t a;
    asm("{ .reg .u64 t; cvta.to.shared.u64 t, %1; cvt.u32.u64 %0, t; }"
        : "=r"(a) : "l"(p));
    return a;
}

__device__ __forceinline__ void cp_async16(uint32_t dst, const void* src) {
    asm volatile("cp.async.ca.shared.global [%0], [%1], 16;"
                 :: "r"(dst), "l"(src));
}
#define CP_COMMIT() asm volatile("cp.async.commit_group;")
#define CP_WAIT0()  asm volatile("cp.async.wait_group 0;" ::: "memory")

#define LDSM_X4(r0, r1, r2, r3, addr) \
    asm volatile("ldmatrix.sync.aligned.m8n8.x4.shared.b16 {%0,%1,%2,%3}, [%4];" \
        : "=r"(r0), "=r"(r1), "=r"(r2), "=r"(r3) : "r"(addr))

#define MMA_F16(d, a, b0, b1) \
    asm volatile("mma.sync.aligned.m16n8k16.row.col.f32.f16.f16.f32 " \
        "{%0,%1,%2,%3}, {%4,%5,%6,%7}, {%8,%9}, {%0,%1,%2,%3};" \
        : "+f"((d)[0]), "+f"((d)[1]), "+f"((d)[2]), "+f"((d)[3]) \
        : "r"((a)[0]), "r"((a)[1]), "r"((a)[2]), "r"((a)[3]), "r"(b0), "r"(b1))

// ---------------- preprocessing --------------------------------------------
__device__ __forceinline__ int edge_at(const void* eiv, long idx) {
    if (g_is64) return (int)((const long long*)eiv)[idx];
    return ((const int*)eiv)[idx];
}

// zero counts + detect dtype + weights -> fp16 [N=128][K]
__global__ void k_init(const int* __restrict__ ei32,
                       const float* __restrict__ W1, const float* __restrict__ W2,
                       const float* __restrict__ Wm, const float* __restrict__ Ws) {
    int i = blockIdx.x * blockDim.x + threadIdx.x;    // 384*256 = 98304
    if (i < NN) g_cnt[i] = 0;
    if (blockIdx.x == 0 && threadIdx.x < 32) {
        int v = ei32[2 * threadIdx.x + 1];
        unsigned m = __ballot_sync(0xffffffffu, v != 0);
        if (threadIdx.x == 0) g_is64 = (m == 0) ? 1 : 0;
    }
    float v;
    if (i < 65536) {
        int n = i >> 9, k = i & 511;
        v = W1[k * 128 + n];
    } else if (i < 81920) {
        int idx = i - 65536;
        int n = idx >> 7, k = idx & 127;
        v = W2[k * 128 + n];
    } else {
        int idx = i - 81920;
        int n = idx >> 7, k = idx & 127;
        v = (n < 64) ? Wm[k * 64 + n] : Ws[k * 64 + (n - 64)];
    }
    g_Bf16[i] = __float2half_rn(v);
}

// per-edge weights, padded to multiple of 8 with w=0 sentinels (warp per node)
__global__ void k_wt() {
    int node = (blockIdx.x * blockDim.x + threadIdx.x) >> 5;
    int lane = threadIdx.x & 31;
    if (node >= NN) return;
    int n = g_cnt[node];
    n = (n < CAP) ? n : CAP;
    int bound = (n + 7) & ~7;
    float dd = rsqrtf((float)(g_cnt[node] + 1));
    const int base = node << 7;
    for (int j = lane; j < bound; j += 32) {
        uint2 sw;
        if (j < n) {
            int s = g_src[base + j];
            sw.x = (unsigned)(s << 8);               // byte offset of fp16 row
            sw.y = __float_as_uint(rsqrtf((float)(g_cnt[s] + 1)) * dd);
        } else {
            sw.x = 0;
            sw.y = 0;
        }
        g_sw[base + j] = sw;
    }
}

// ---------------- fp16 tensor-core GEMM, fp16 output -----------------------
// 128x128 CTA tile, 8 warps of 32x64. FUSE: blocks >= GB run edge scatter.
// APRE: A is fp16 rows in global (from k_agg) -> cp.async path.
static constexpr int ROWB   = 80;                 // padded 32-elem fp16 row
static constexpr int AHALF  = 128 * ROWB;         // 10240
static constexpr int STAGE  = 2 * AHALF;          // A | B
static constexpr int GEMM_SMEM = 2 * STAGE;       // 40960

template <int K, int FUSE, int APRE>
__global__ __launch_bounds__(256, 3) void k_tgemm(
    const float* __restrict__ A,
    const __half* __restrict__ Ah,
    const __half* __restrict__ Bf,
    __half* __restrict__ C, const void* __restrict__ eiv)
{
    if (FUSE && blockIdx.x >= GB) {                 // edge-scatter role
        int e = (blockIdx.x - GB) * 256 + threadIdx.x;
        if (e < EE) {
            int s = edge_at(eiv, e);
            int d = edge_at(eiv, (long)EE + e);
            int pos = atomicAdd(&g_cnt[d], 1);
            if (pos < CAP) g_src[(d << 7) + pos] = s;
        }
        return;
    }

    extern __shared__ __align__(256) char smem[];
    constexpr int NCH = K / 32;
    const int tid  = threadIdx.x;
    const int wid  = tid >> 5;
    const int lane = tid & 31;
    const int warp_m = wid & 3;
    const int warp_n = wid >> 2;
    const uint32_t sb = smem_u32(smem);
    const int rowBase = blockIdx.x * 128;

    const uint32_t a_off = (uint32_t)(((lane & 7) + ((lane >> 3) & 1) * 8) * ROWB
                                      + ((lane >> 4) & 1) * 16);
    const uint32_t b_off = (uint32_t)((((lane >> 4) & 1) * 8 + (lane & 7)) * ROWB
                                      + ((lane >> 3) & 1) * 16);

    float acc[2][8][4];
#pragma unroll
    for (int t = 0; t < 2; t++)
#pragma unroll
        for (int j = 0; j < 8; j++)
#pragma unroll
            for (int v = 0; v < 4; v++) acc[t][j][v] = 0.f;

    const int ar = tid >> 1;          // 128 rows, 2 thr/row
    const int aq = (tid & 1) * 4;     // fp32 A path: quad base (4 iters)
    const int br = tid >> 1;
    const int bq = (tid & 1) << 1;    // 16B chunk base (2 iters)

    auto cpB = [&](int c, int s) {
        uint32_t stb = sb + s * STAGE;
#pragma unroll
        for (int it = 0; it < 2; it++) {
            int q = bq + it;
            uint32_t off = (uint32_t)(br * ROWB + q * 16);
            size_t idx = (size_t)br * K + c * 32 + q * 8;
            cp_async16(stb + AHALF + off, Bf + idx);
        }
        CP_COMMIT();
    };

    auto cpA = [&](int c, int s) {    // APRE path (fp16 rows in global)
        uint32_t stb = sb + s * STAGE;
        int row = rowBase + br;
        if (row < NN) {
#pragma unroll
            for (int it = 0; it < 2; it++) {
                int q = bq + it;
                uint32_t off = (uint32_t)(br * ROWB + q * 16);
                size_t idx = (size_t)row * K + c * 32 + q * 8;
                cp_async16(stb + off, Ah + idx);
            }
        }
        CP_COMMIT();
    };

    auto ldgA = [&](int c, float4* pa) {
#pragma unroll
        for (int it = 0; it < 4; it++) {
            int q = aq + it;
            int row = rowBase + ar;
            float4 v = make_float4(0.f, 0.f, 0.f, 0.f);
            if (row < NN)
                v = *reinterpret_cast<const float4*>(&A[(size_t)row * K + c * 32 + q * 4]);
            pa[it] = v;
        }
    };

    auto stsA = [&](int s, const float4* pa) {   // fp32 -> fp16
        char* st = smem + s * STAGE;
#pragma unroll
        for (int it = 0; it < 4; it++) {
            int q = aq + it;
            float4 v = pa[it];
            __half2 h01 = __floats2half2_rn(v.x, v.y);
            __half2 h23 = __floats2half2_rn(v.z, v.w);
            uint32_t off = (uint32_t)(ar * ROWB + q * 8);
            *reinterpret_cast<__half2*>(st + off)     = h01;
            *reinterpret_cast<__half2*>(st + off + 4) = h23;
        }
    };

    {   // prologue: chunk 0 -> stage 0
        if (APRE) {
            cpA(0, 0);
            cpB(0, 0);
        } else {
            float4 pa[4];
            ldgA(0, pa);
            cpB(0, 0);
            stsA(0, pa);
        }
        CP_WAIT0();
    }
    __syncthreads();

    for (int c = 0; c < NCH; c++) {
        const int s = c & 1;
        float4 pa[4];
        if (c + 1 < NCH) {
            if (APRE) {
                cpA(c + 1, s ^ 1);
                cpB(c + 1, s ^ 1);
            } else {
                ldgA(c + 1, pa);
                cpB(c + 1, s ^ 1);
            }
        }

        const uint32_t aBaseH = sb + s * STAGE + (uint32_t)(warp_m * 32) * ROWB;
        const uint32_t bBaseH = sb + s * STAGE + AHALF + (uint32_t)(warp_n * 64) * ROWB;

#pragma unroll
        for (int sk = 0; sk < 2; sk++) {
            uint32_t ah[2][4];
#pragma unroll
            for (int t = 0; t < 2; t++) {
                uint32_t ad = aBaseH + (uint32_t)(t * 16 * ROWB + sk * 32) + a_off;
                LDSM_X4(ah[t][0], ah[t][1], ah[t][2], ah[t][3], ad);
            }
#pragma unroll
            for (int jp = 0; jp < 4; jp++) {
                uint32_t bf[4];
                uint32_t bd = bBaseH + (uint32_t)(jp * 16 * ROWB + sk * 32) + b_off;
                LDSM_X4(bf[0], bf[1], bf[2], bf[3], bd);
#pragma unroll
                for (int t = 0; t < 2; t++)
#pragma unroll
                    for (int jj = 0; jj < 2; jj++) {
                        int j = jp * 2 + jj, o = jj * 2;
                        MMA_F16(acc[t][j], ah[t], bf[o], bf[o + 1]);
                    }
            }
        }

        if (c + 1 < NCH) {
            if (!APRE) stsA(s ^ 1, pa);
            CP_WAIT0();
        }
        __syncthreads();
    }

    // epilogue: fp16 stores
    const int r0 = rowBase + warp_m * 32 + (lane >> 2);
    const int cb = (lane & 3) * 2;
#pragma unroll
    for (int t = 0; t < 2; t++) {
#pragma unroll
        for (int j = 0; j < 8; j++) {
            int col = warp_n * 64 + j * 8 + cb;
            int ra = r0 + t * 16;
            int rb = ra + 8;
            if (ra < NN)
                *reinterpret_cast<__half2*>(&C[(size_t)ra * 128 + col]) =
                    __floats2half2_rn(acc[t][j][0], acc[t][j][1]);
            if (rb < NN)
                *reinterpret_cast<__half2*>(&C[(size_t)rb * 128 + col]) =
                    __floats2half2_rn(acc[t][j][2], acc[t][j][3]);
        }
    }
}

// ---------------- aggregation: branch-free, 2 edges/warp-iter --------------
// Warp = one node. Lanes 0-15 handle edge j (features fl*8..+8 via uint4),
// lanes 16-31 handle edge j+1; halves combined by shfl_xor(16) at the end.
// Edge list pre-padded (k_wt) to multiple of 2 with w=0 -> no predication.
// MODE 1: h = relu(sum + biasA) -> fp16 rows (next GEMM A input)
// MODE 2: cols 0-63 -> OA + biasA, cols 64-127 -> OB + biasB (fp32 [node][64])
template <int MODE>
__global__ __launch_bounds__(128) void k_agg(
    const __half* __restrict__ G,   // fp16 table rows (256B each)
    const float* __restrict__ biasA, const float* __restrict__ biasB,
    float* __restrict__ OA, float* __restrict__ OB,
    __half* __restrict__ Hh)
{
    int node = (blockIdx.x * blockDim.x + threadIdx.x) >> 5;
    int lane = threadIdx.x & 31;
    if (node >= NN) return;
    int nraw = g_cnt[node];
    int n = (nraw < CAP) ? nraw : CAP;
    int bound = (n + 7) & ~7;
    const int base = node << 7;
    const int half = lane >> 4;
    const int fl   = lane & 15;
    const uint32_t flo = (uint32_t)(fl * 16);
    const char* Gc = (const char*)G;
    float dd = rsqrtf((float)(nraw + 1));

    float acc[8];
    {   // self loop term (half 0 only; half 1 contributes 0)
        uint4 r = *reinterpret_cast<const uint4*>(Gc + ((size_t)node << 8) + flo);
        const __half2* h = reinterpret_cast<const __half2*>(&r);
        float wself = half ? 0.f : dd * dd;
#pragma unroll
        for (int q = 0; q < 4; q++) {
            float2 f = __half22float2(h[q]);
            acc[q * 2]     = wself * f.x;
            acc[q * 2 + 1] = wself * f.y;
        }
    }

    const uint2* swp = &g_sw[base + half];
#pragma unroll 4
    for (int j = 0; j < bound; j += 2) {
        uint2 sw = swp[j];                       // {row byte offset, w}
        float w = __uint_as_float(sw.y);
        uint4 m = *reinterpret_cast<const uint4*>(Gc + sw.x + flo);
        const __half2* h = reinterpret_cast<const __half2*>(&m);
#pragma unroll
        for (int q = 0; q < 4; q++) {
            float2 f = __half22float2(h[q]);
            acc[q * 2]     = fmaf(w, f.x, acc[q * 2]);
            acc[q * 2 + 1] = fmaf(w, f.y, acc[q * 2 + 1]);
        }
    }

    // combine halves
#pragma unroll
    for (int q = 0; q < 8; q++)
        acc[q] += __shfl_xor_sync(0xffffffffu, acc[q], 16);

    if (half == 0) {
        if (MODE == 1) {
            float4 b0 = reinterpret_cast<const float4*>(biasA)[fl * 2];
            float4 b1 = reinterpret_cast<const float4*>(biasA)[fl * 2 + 1];
            float r0 = fmaxf(acc[0] + b0.x, 0.f);
            float r1 = fmaxf(acc[1] + b0.y, 0.f);
            float r2 = fmaxf(acc[2] + b0.z, 0.f);
            float r3 = fmaxf(acc[3] + b0.w, 0.f);
            float r4 = fmaxf(acc[4] + b1.x, 0.f);
            float r5 = fmaxf(acc[5] + b1.y, 0.f);
            float r6 = fmaxf(acc[6] + b1.z, 0.f);
            float r7 = fmaxf(acc[7] + b1.w, 0.f);
            __half2 h0 = __floats2half2_rn(r0, r1);
            __half2 h1 = __floats2half2_rn(r2, r3);
            __half2 h2 = __floats2half2_rn(r4, r5);
            __half2 h3 = __floats2half2_rn(r6, r7);
            uint4 hv;
            hv.x = *reinterpret_cast<uint32_t*>(&h0);
            hv.y = *reinterpret_cast<uint32_t*>(&h1);
            hv.z = *reinterpret_cast<uint32_t*>(&h2);
            hv.w = *reinterpret_cast<uint32_t*>(&h3);
            *reinterpret_cast<uint4*>(Hh + (size_t)node * 128 + fl * 8) = hv;
        } else {
            float*       O    = (fl < 8) ? OA : OB;
            const float* bias = (fl < 8) ? biasA : biasB;
            int f = (fl & 7) * 8;
            float4 b0 = *reinterpret_cast<const float4*>(&bias[f]);
            float4 b1 = *reinterpret_cast<const float4*>(&bias[f + 4]);
            float4 v0 = make_float4(acc[0] + b0.x, acc[1] + b0.y,
                                    acc[2] + b0.z, acc[3] + b0.w);
            float4 v1 = make_float4(acc[4] + b1.x, acc[5] + b1.y,
                                    acc[6] + b1.z, acc[7] + b1.w);
            *reinterpret_cast<float4*>(&O[(size_t)node * 64 + f])     = v0;
            *reinterpret_cast<float4*>(&O[(size_t)node * 64 + f + 4]) = v1;
        }
    }
}

// ---------------- launch ----------------------------------------------------
extern "C" void kernel_launch(void* const* d_in, const int* in_sizes, int n_in,
                              void* d_out, int out_size) {
    const float* x  = (const float*)d_in[0];
    const void*  ei = d_in[1];
    const float* W1 = (const float*)d_in[2];
    const float* b1 = (const float*)d_in[3];
    const float* W2 = (const float*)d_in[4];
    const float* b2 = (const float*)d_in[5];
    const float* Wm = (const float*)d_in[6];
    const float* bm = (const float*)d_in[7];
    const float* Ws = (const float*)d_in[8];
    const float* bs = (const float*)d_in[9];
    float* outM = (float*)d_out;
    float* outS = outM + (long)NN * ZD;

    float*  pA  = nullptr;
    __half* pH  = nullptr;
    __half* pBf = nullptr;
    cudaGetSymbolAddress((void**)&pA,  g_bufA);
    cudaGetSymbolAddress((void**)&pH,  g_H16);
    cudaGetSymbolAddress((void**)&pBf, g_Bf16);
    __half* pAh = (__half*)pA;                       // alias g_bufA

    cudaFuncSetAttribute(k_tgemm<512, 1, 0>, cudaFuncAttributeMaxDynamicSharedMemorySize, GEMM_SMEM);
    cudaFuncSetAttribute(k_tgemm<128, 0, 1>, cudaFuncAttributeMaxDynamicSharedMemorySize, GEMM_SMEM);

    const int T = 256;
    const int ab = (NN * 32 + 127) / 128;      // agg blocks (128 thr)
    const int wb = (NN * 32 + T - 1) / T;      // k_wt blocks

    // init: zero counts + dtype detect + all weight fp16 (1 launch)
    k_init<<<384, T>>>((const int*)ei, W1, W2, Wm, Ws);

    // GEMM1 (single-fp16 A) fused with edge scatter (tail absorption)
    k_tgemm<512, 1, 0><<<GB + EB, T, GEMM_SMEM>>>(x, nullptr, pBf, pH, ei);
    k_wt<<<wb, T>>>();
    k_agg<1><<<ab, 128>>>(pH, b1, nullptr, nullptr, nullptr, pAh);
    // layer 2 (single-fp16 A via cp.async)
    k_tgemm<128, 0, 1><<<GB, T, GEMM_SMEM>>>(nullptr, pAh, pBf + 65536, pH, nullptr);
    k_agg<1><<<ab, 128>>>(pH, b2, nullptr, nullptr, nullptr, pAh);
    // heads (single-fp16 A)
    k_tgemm<128, 0, 1><<<GB, T, GEMM_SMEM>>>(nullptr, pAh, pBf + 81920, pH, nullptr);
    k_agg<2><<<ab, 128>>>(pH, bm, bs, outM, outS, nullptr);
}

// round 15
// speedup vs baseline: 1.1928x; 1.1928x over previous
#include <cuda_runtime.h>
#include <cuda_bf16.h>
#include <cuda_fp16.h>
#include <cstdint>

#define NN 50000
#define EE 800000
#define FD 128
#define ZD 64
#define CAP 128          // bucket capacity per node (Poisson(16); overflow ~1e-18)

static constexpr int GB = (NN + 127) / 128;          // 391 GEMM tiles
static constexpr int EB = (EE + 255) / 256;          // 3125 edge blocks

// ---------------- scratch (device globals; no allocation allowed) ----------
__device__ __align__(256) float  g_bufA[NN * FD];    // aliased: fp16 A rows
__device__ __align__(256) __half g_H16[NN * FD];
__device__ __align__(256) __half g_Bf16[128 * 512 + 2 * 128 * 128];
__device__ __align__(256) int    g_src[NN * CAP];
__device__ __align__(256) uint2  g_sw[NN * CAP];     // packed {s<<8, w}, padded to 8
__device__ int   g_cnt[NN];
__device__ int   g_is64;

// ---------------- PTX helpers ----------------------------------------------
__device__ __forceinline__ uint32_t smem_u32(const void* p) {
    uint32_t a;
    asm("{ .reg .u64 t; cvta.to.shared.u64 t, %1; cvt.u32.u64 %0, t; }"
        : "=r"(a) : "l"(p));
    return a;
}

__device__ __forceinline__ void cp_async16(uint32_t dst, const void* src) {
    asm volatile("cp.async.ca.shared.global [%0], [%1], 16;"
                 :: "r"(dst), "l"(src));
}
#define CP_COMMIT() asm volatile("cp.async.commit_group;")
#define CP_WAIT0()  asm volatile("cp.async.wait_group 0;" ::: "memory")

#define LDSM_X4(r0, r1, r2, r3, addr) \
    asm volatile("ldmatrix.sync.aligned.m8n8.x4.shared.b16 {%0,%1,%2,%3}, [%4];" \
        : "=r"(r0), "=r"(r1), "=r"(r2), "=r"(r3) : "r"(addr))

#define MMA_F16(d, a, b0, b1) \
    asm volatile("mma.sync.aligned.m16n8k16.row.col.f32.f16.f16.f32 " \
        "{%0,%1,%2,%3}, {%4,%5,%6,%7}, {%8,%9}, {%0,%1,%2,%3};" \
        : "+f"((d)[0]), "+f"((d)[1]), "+f"((d)[2]), "+f"((d)[3]) \
        : "r"((a)[0]), "r"((a)[1]), "r"((a)[2]), "r"((a)[3]), "r"(b0), "r"(b1))

// ---------------- preprocessing --------------------------------------------
__device__ __forceinline__ int edge_at(const void* eiv, long idx) {
    if (g_is64) return (int)((const long long*)eiv)[idx];
    return ((const int*)eiv)[idx];
}

// zero counts + detect dtype + weights -> fp16 [N=128][K]
__global__ void k_init(const int* __restrict__ ei32,
                       const float* __restrict__ W1, const float* __restrict__ W2,
                       const float* __restrict__ Wm, const float* __restrict__ Ws) {
    int i = blockIdx.x * blockDim.x + threadIdx.x;    // 384*256 = 98304
    if (i < NN) g_cnt[i] = 0;
    if (blockIdx.x == 0 && threadIdx.x < 32) {
        int v = ei32[2 * threadIdx.x + 1];
        unsigned m = __ballot_sync(0xffffffffu, v != 0);
        if (threadIdx.x == 0) g_is64 = (m == 0) ? 1 : 0;
    }
    float v;
    if (i < 65536) {
        int n = i >> 9, k = i & 511;
        v = W1[k * 128 + n];
    } else if (i < 81920) {
        int idx = i - 65536;
        int n = idx >> 7, k = idx & 127;
        v = W2[k * 128 + n];
    } else {
        int idx = i - 81920;
        int n = idx >> 7, k = idx & 127;
        v = (n < 64) ? Wm[k * 64 + n] : Ws[k * 64 + (n - 64)];
    }
    g_Bf16[i] = __float2half_rn(v);
}

// per-edge weights, padded to multiple of 8 with w=0 sentinels (warp per node)
__global__ void k_wt() {
    int node = (blockIdx.x * blockDim.x + threadIdx.x) >> 5;
    int lane = threadIdx.x & 31;
    if (node >= NN) return;
    int n = g_cnt[node];
    n = (n < CAP) ? n : CAP;
    int bound = (n + 7) & ~7;
    float dd = rsqrtf((float)(g_cnt[node] + 1));
    const int base = node << 7;
    for (int j = lane; j < bound; j += 32) {
        uint2 sw;
        if (j < n) {
            int s = g_src[base + j];
            sw.x = (unsigned)(s << 8);               // byte offset of fp16 row
            sw.y = __float_as_uint(rsqrtf((float)(g_cnt[s] + 1)) * dd);
        } else {
            sw.x = 0;
            sw.y = 0;
        }
        g_sw[base + j] = sw;
    }
}

// ---------------- fp16 tensor-core GEMM, fp16 output -----------------------
// 128x128 CTA tile, 8 warps of 32x64. FUSE: blocks >= GB run edge scatter.
// APRE: A is fp16 rows in global (from k_agg) -> cp.async path.
static constexpr int ROWB   = 80;                 // padded 32-elem fp16 row
static constexpr int AHALF  = 128 * ROWB;         // 10240
static constexpr int STAGE  = 2 * AHALF;          // A | B
static constexpr int GEMM_SMEM = 2 * STAGE;       // 40960

template <int K, int FUSE, int APRE>
__global__ __launch_bounds__(256, 2) void k_tgemm(
    const float* __restrict__ A,
    const __half* __restrict__ Ah,
    const __half* __restrict__ Bf,
    __half* __restrict__ C, const void* __restrict__ eiv)
{
    if (FUSE && blockIdx.x >= GB) {                 // edge-scatter role
        int e = (blockIdx.x - GB) * 256 + threadIdx.x;
        if (e < EE) {
            int s = edge_at(eiv, e);
            int d = edge_at(eiv, (long)EE + e);
            int pos = atomicAdd(&g_cnt[d], 1);
            if (pos < CAP) g_src[(d << 7) + pos] = s;
        }
        return;
    }

    extern __shared__ __align__(256) char smem[];
    constexpr int NCH = K / 32;
    const int tid  = threadIdx.x;
    const int wid  = tid >> 5;
    const int lane = tid & 31;
    const int warp_m = wid & 3;
    const int warp_n = wid >> 2;
    const uint32_t sb = smem_u32(smem);
    const int rowBase = blockIdx.x * 128;

    const uint32_t a_off = (uint32_t)(((lane & 7) + ((lane >> 3) & 1) * 8) * ROWB
                                      + ((lane >> 4) & 1) * 16);
    const uint32_t b_off = (uint32_t)((((lane >> 4) & 1) * 8 + (lane & 7)) * ROWB
                                      + ((lane >> 3) & 1) * 16);

    float acc[2][8][4];
#pragma unroll
    for (int t = 0; t < 2; t++)
#pragma unroll
        for (int j = 0; j < 8; j++)
#pragma unroll
            for (int v = 0; v < 4; v++) acc[t][j][v] = 0.f;

    const int ar = tid >> 1;          // 128 rows, 2 thr/row
    const int aq = (tid & 1) * 4;     // fp32 A path: quad base (4 iters)
    const int br = tid >> 1;
    const int bq = (tid & 1) << 1;    // 16B chunk base (2 iters)

    auto cpB = [&](int c, int s) {
        uint32_t stb = sb + s * STAGE;
#pragma unroll
        for (int it = 0; it < 2; it++) {
            int q = bq + it;
            uint32_t off = (uint32_t)(br * ROWB + q * 16);
            size_t idx = (size_t)br * K + c * 32 + q * 8;
            cp_async16(stb + AHALF + off, Bf + idx);
        }
        CP_COMMIT();
    };

    auto cpA = [&](int c, int s) {    // APRE path (fp16 rows in global)
        uint32_t stb = sb + s * STAGE;
        int row = rowBase + br;
        if (row < NN) {
#pragma unroll
            for (int it = 0; it < 2; it++) {
                int q = bq + it;
                uint32_t off = (uint32_t)(br * ROWB + q * 16);
                size_t idx = (size_t)row * K + c * 32 + q * 8;
                cp_async16(stb + off, Ah + idx);
            }
        }
        CP_COMMIT();
    };

    auto ldgA = [&](int c, float4* pa) {
#pragma unroll
        for (int it = 0; it < 4; it++) {
            int q = aq + it;
            int row = rowBase + ar;
            float4 v = make_float4(0.f, 0.f, 0.f, 0.f);
            if (row < NN)
                v = *reinterpret_cast<const float4*>(&A[(size_t)row * K + c * 32 + q * 4]);
            pa[it] = v;
        }
    };

    auto stsA = [&](int s, const float4* pa) {   // fp32 -> fp16
        char* st = smem + s * STAGE;
#pragma unroll
        for (int it = 0; it < 4; it++) {
            int q = aq + it;
            float4 v = pa[it];
            __half2 h01 = __floats2half2_rn(v.x, v.y);
            __half2 h23 = __floats2half2_rn(v.z, v.w);
            uint32_t off = (uint32_t)(ar * ROWB + q * 8);
            *reinterpret_cast<__half2*>(st + off)     = h01;
            *reinterpret_cast<__half2*>(st + off + 4) = h23;
        }
    };

    {   // prologue: chunk 0 -> stage 0
        if (APRE) {
            cpA(0, 0);
            cpB(0, 0);
        } else {
            float4 pa[4];
            ldgA(0, pa);
            cpB(0, 0);
            stsA(0, pa);
        }
        CP_WAIT0();
    }
    __syncthreads();

    for (int c = 0; c < NCH; c++) {
        const int s = c & 1;
        float4 pa[4];
        if (c + 1 < NCH) {
            if (APRE) {
                cpA(c + 1, s ^ 1);
                cpB(c + 1, s ^ 1);
            } else {
                ldgA(c + 1, pa);
                cpB(c + 1, s ^ 1);
            }
        }

        const uint32_t aBaseH = sb + s * STAGE + (uint32_t)(warp_m * 32) * ROWB;
        const uint32_t bBaseH = sb + s * STAGE + AHALF + (uint32_t)(warp_n * 64) * ROWB;

#pragma unroll
        for (int sk = 0; sk < 2; sk++) {
            uint32_t ah[2][4];
#pragma unroll
            for (int t = 0; t < 2; t++) {
                uint32_t ad = aBaseH + (uint32_t)(t * 16 * ROWB + sk * 32) + a_off;
                LDSM_X4(ah[t][0], ah[t][1], ah[t][2], ah[t][3], ad);
            }
#pragma unroll
            for (int jp = 0; jp < 4; jp++) {
                uint32_t bf[4];
                uint32_t bd = bBaseH + (uint32_t)(jp * 16 * ROWB + sk * 32) + b_off;
                LDSM_X4(bf[0], bf[1], bf[2], bf[3], bd);
#pragma unroll
                for (int t = 0; t < 2; t++)
#pragma unroll
                    for (int jj = 0; jj < 2; jj++) {
                        int j = jp * 2 + jj, o = jj * 2;
                        MMA_F16(acc[t][j], ah[t], bf[o], bf[o + 1]);
                    }
            }
        }

        if (c + 1 < NCH) {
            if (!APRE) stsA(s ^ 1, pa);
            CP_WAIT0();
        }
        __syncthreads();
    }

    // epilogue: fp16 stores
    const int r0 = rowBase + warp_m * 32 + (lane >> 2);
    const int cb = (lane & 3) * 2;
#pragma unroll
    for (int t = 0; t < 2; t++) {
#pragma unroll
        for (int j = 0; j < 8; j++) {
            int col = warp_n * 64 + j * 8 + cb;
            int ra = r0 + t * 16;
            int rb = ra + 8;
            if (ra < NN)
                *reinterpret_cast<__half2*>(&C[(size_t)ra * 128 + col]) =
                    __floats2half2_rn(acc[t][j][0], acc[t][j][1]);
            if (rb < NN)
                *reinterpret_cast<__half2*>(&C[(size_t)rb * 128 + col]) =
                    __floats2half2_rn(acc[t][j][2], acc[t][j][3]);
        }
    }
}

// ---------------- aggregation: branch-free, 2 edges/warp-iter --------------
// Warp = one node. Lanes 0-15 handle edge j (features fl*8..+8 via uint4),
// lanes 16-31 handle edge j+1; halves combined by shfl_xor(16) at the end.
// Edge list pre-padded (k_wt) to multiple of 2 with w=0 -> no predication.
// MODE 1: h = relu(sum + biasA) -> fp16 rows (next GEMM A input)
// MODE 2: cols 0-63 -> OA + biasA, cols 64-127 -> OB + biasB (fp32 [node][64])
template <int MODE>
__global__ __launch_bounds__(128) void k_agg(
    const __half* __restrict__ G,   // fp16 table rows (256B each)
    const float* __restrict__ biasA, const float* __restrict__ biasB,
    float* __restrict__ OA, float* __restrict__ OB,
    __half* __restrict__ Hh)
{
    int node = (blockIdx.x * blockDim.x + threadIdx.x) >> 5;
    int lane = threadIdx.x & 31;
    if (node >= NN) return;
    int nraw = g_cnt[node];
    int n = (nraw < CAP) ? nraw : CAP;
    int bound = (n + 7) & ~7;
    const int base = node << 7;
    const int half = lane >> 4;
    const int fl   = lane & 15;
    const uint32_t flo = (uint32_t)(fl * 16);
    const char* Gc = (const char*)G;
    float dd = rsqrtf((float)(nraw + 1));

    float acc[8];
    {   // self loop term (half 0 only; half 1 contributes 0)
        uint4 r = *reinterpret_cast<const uint4*>(Gc + ((size_t)node << 8) + flo);
        const __half2* h = reinterpret_cast<const __half2*>(&r);
        float wself = half ? 0.f : dd * dd;
#pragma unroll
        for (int q = 0; q < 4; q++) {
            float2 f = __half22float2(h[q]);
            acc[q * 2]     = wself * f.x;
            acc[q * 2 + 1] = wself * f.y;
        }
    }

    const uint2* swp = &g_sw[base + half];
#pragma unroll 4
    for (int j = 0; j < bound; j += 2) {
        uint2 sw = swp[j];                       // {row byte offset, w}
        float w = __uint_as_float(sw.y);
        uint4 m = *reinterpret_cast<const uint4*>(Gc + sw.x + flo);
        const __half2* h = reinterpret_cast<const __half2*>(&m);
#pragma unroll
        for (int q = 0; q < 4; q++) {
            float2 f = __half22float2(h[q]);
            acc[q * 2]     = fmaf(w, f.x, acc[q * 2]);
            acc[q * 2 + 1] = fmaf(w, f.y, acc[q * 2 + 1]);
        }
    }

    // combine halves
#pragma unroll
    for (int q = 0; q < 8; q++)
        acc[q] += __shfl_xor_sync(0xffffffffu, acc[q], 16);

    if (half == 0) {
        if (MODE == 1) {
            float4 b0 = reinterpret_cast<const float4*>(biasA)[fl * 2];
            float4 b1 = reinterpret_cast<const float4*>(biasA)[fl * 2 + 1];
            float r0 = fmaxf(acc[0] + b0.x, 0.f);
            float r1 = fmaxf(acc[1] + b0.y, 0.f);
            float r2 = fmaxf(acc[2] + b0.z, 0.f);
            float r3 = fmaxf(acc[3] + b0.w, 0.f);
            float r4 = fmaxf(acc[4] + b1.x, 0.f);
            float r5 = fmaxf(acc[5] + b1.y, 0.f);
            float r6 = fmaxf(acc[6] + b1.z, 0.f);
            float r7 = fmaxf(acc[7] + b1.w, 0.f);
            __half2 h0 = __floats2half2_rn(r0, r1);
            __half2 h1 = __floats2half2_rn(r2, r3);
            __half2 h2 = __floats2half2_rn(r4, r5);
            __half2 h3 = __floats2half2_rn(r6, r7);
            uint4 hv;
            hv.x = *reinterpret_cast<uint32_t*>(&h0);
            hv.y = *reinterpret_cast<uint32_t*>(&h1);
            hv.z = *reinterpret_cast<uint32_t*>(&h2);
            hv.w = *reinterpret_cast<uint32_t*>(&h3);
            *reinterpret_cast<uint4*>(Hh + (size_t)node * 128 + fl * 8) = hv;
        } else {
            float*       O    = (fl < 8) ? OA : OB;
            const float* bias = (fl < 8) ? biasA : biasB;
            int f = (fl & 7) * 8;
            float4 b0 = *reinterpret_cast<const float4*>(&bias[f]);
            float4 b1 = *reinterpret_cast<const float4*>(&bias[f + 4]);
            float4 v0 = make_float4(acc[0] + b0.x, acc[1] + b0.y,
                                    acc[2] + b0.z, acc[3] + b0.w);
            float4 v1 = make_float4(acc[4] + b1.x, acc[5] + b1.y,
                                    acc[6] + b1.z, acc[7] + b1.w);
            *reinterpret_cast<float4*>(&O[(size_t)node * 64 + f])     = v0;
            *reinterpret_cast<float4*>(&O[(size_t)node * 64 + f + 4]) = v1;
        }
    }
}

// ---------------- launch ----------------------------------------------------
extern "C" void kernel_launch(void* const* d_in, const int* in_sizes, int n_in,
                              void* d_out, int out_size) {
    const float* x  = (const float*)d_in[0];
    const void*  ei = d_in[1];
    const float* W1 = (const float*)d_in[2];
    const float* b1 = (const float*)d_in[3];
    const float* W2 = (const float*)d_in[4];
    const float* b2 = (const float*)d_in[5];
    const float* Wm = (const float*)d_in[6];
    const float* bm = (const float*)d_in[7];
    const float* Ws = (const float*)d_in[8];
    const float* bs = (const float*)d_in[9];
    float* outM = (float*)d_out;
    float* outS = outM + (long)NN * ZD;

    float*  pA  = nullptr;
    __half* pH  = nullptr;
    __half* pBf = nullptr;
    cudaGetSymbolAddress((void**)&pA,  g_bufA);
    cudaGetSymbolAddress((void**)&pH,  g_H16);
    cudaGetSymbolAddress((void**)&pBf, g_Bf16);
    __half* pAh = (__half*)pA;                       // alias g_bufA

    cudaFuncSetAttribute(k_tgemm<512, 1, 0>, cudaFuncAttributeMaxDynamicSharedMemorySize, GEMM_SMEM);
    cudaFuncSetAttribute(k_tgemm<128, 0, 1>, cudaFuncAttributeMaxDynamicSharedMemorySize, GEMM_SMEM);

    const int T = 256;
    const int ab = (NN * 32 + 127) / 128;      // agg blocks (128 thr)
    const int wb = (NN * 32 + T - 1) / T;      // k_wt blocks

    // init: zero counts + dtype detect + all weight fp16 (1 launch)
    k_init<<<384, T>>>((const int*)ei, W1, W2, Wm, Ws);

    // GEMM1 (single-fp16 A) fused with edge scatter (tail absorption)
    k_tgemm<512, 1, 0><<<GB + EB, T, GEMM_SMEM>>>(x, nullptr, pBf, pH, ei);
    k_wt<<<wb, T>>>();
    k_agg<1><<<ab, 128>>>(pH, b1, nullptr, nullptr, nullptr, pAh);
    // layer 2 (single-fp16 A via cp.async)
    k_tgemm<128, 0, 1><<<GB, T, GEMM_SMEM>>>(nullptr, pAh, pBf + 65536, pH, nullptr);
    k_agg<1><<<ab, 128>>>(pH, b2, nullptr, nullptr, nullptr, pAh);
    // heads (single-fp16 A)
    k_tgemm<128, 0, 1><<<GB, T, GEMM_SMEM>>>(nullptr, pAh, pBf + 81920, pH, nullptr);
    k_agg<2><<<ab, 128>>>(pH, bm, bs, outM, outS, nullptr);
}

// round 16
// speedup vs baseline: 1.1930x; 1.0002x over previous
#include <cuda_runtime.h>
#include <cuda_bf16.h>
#include <cuda_fp16.h>
#include <cstdint>

#define NN 50000
#define EE 800000
#define FD 128
#define ZD 64
#define CAP 128          // bucket capacity per node (Poisson(16); overflow ~1e-18)

static constexpr int TM = 64;                        // GEMM tile rows
static constexpr int GB = (NN + TM - 1) / TM;        // 782 GEMM tiles
static constexpr int EB = (EE + 255) / 256;          // 3125 edge blocks

// ---------------- scratch (device globals; no allocation allowed) ----------
__device__ __align__(256) float  g_bufA[NN * FD];    // aliased: fp16 A rows
__device__ __align__(256) __half g_H16[NN * FD];
__device__ __align__(256) __half g_Bf16[128 * 512 + 2 * 128 * 128];
__device__ __align__(256) int    g_src[NN * CAP];
__device__ __align__(256) uint2  g_sw[NN * CAP];     // packed {s<<8, w}, padded to 8
__device__ int   g_cnt[NN];
__device__ int   g_is64;

// ---------------- PTX helpers ----------------------------------------------
__device__ __forceinline__ uint32_t smem_u32(const void* p) {
    uint32_t a;
    asm("{ .reg .u64 t; cvta.to.shared.u64 t, %1; cvt.u32.u64 %0, t; }"
        : "=r"(a) : "l"(p));
    return a;
}

__device__ __forceinline__ void cp_async16(uint32_t dst, const void* src) {
    asm volatile("cp.async.ca.shared.global [%0], [%1], 16;"
                 :: "r"(dst), "l"(src));
}
#define CP_COMMIT() asm volatile("cp.async.commit_group;")
#define CP_WAIT0()  asm volatile("cp.async.wait_group 0;" ::: "memory")

#define LDSM_X4(r0, r1, r2, r3, addr) \
    asm volatile("ldmatrix.sync.aligned.m8n8.x4.shared.b16 {%0,%1,%2,%3}, [%4];" \
        : "=r"(r0), "=r"(r1), "=r"(r2), "=r"(r3) : "r"(addr))

#define MMA_F16(d, a, b0, b1) \
    asm volatile("mma.sync.aligned.m16n8k16.row.col.f32.f16.f16.f32 " \
        "{%0,%1,%2,%3}, {%4,%5,%6,%7}, {%8,%9}, {%0,%1,%2,%3};" \
        : "+f"((d)[0]), "+f"((d)[1]), "+f"((d)[2]), "+f"((d)[3]) \
        : "r"((a)[0]), "r"((a)[1]), "r"((a)[2]), "r"((a)[3]), "r"(b0), "r"(b1))

// ---------------- preprocessing --------------------------------------------
__device__ __forceinline__ int edge_at(const void* eiv, long idx) {
    if (g_is64) return (int)((const long long*)eiv)[idx];
    return ((const int*)eiv)[idx];
}

// zero counts + detect dtype + weights -> fp16 [N=128][K]
__global__ void k_init(const int* __restrict__ ei32,
                       const float* __restrict__ W1, const float* __restrict__ W2,
                       const float* __restrict__ Wm, const float* __restrict__ Ws) {
    int i = blockIdx.x * blockDim.x + threadIdx.x;    // 384*256 = 98304
    if (i < NN) g_cnt[i] = 0;
    if (blockIdx.x == 0 && threadIdx.x < 32) {
        int v = ei32[2 * threadIdx.x + 1];
        unsigned m = __ballot_sync(0xffffffffu, v != 0);
        if (threadIdx.x == 0) g_is64 = (m == 0) ? 1 : 0;
    }
    float v;
    if (i < 65536) {
        int n = i >> 9, k = i & 511;
        v = W1[k * 128 + n];
    } else if (i < 81920) {
        int idx = i - 65536;
        int n = idx >> 7, k = idx & 127;
        v = W2[k * 128 + n];
    } else {
        int idx = i - 81920;
        int n = idx >> 7, k = idx & 127;
        v = (n < 64) ? Wm[k * 64 + n] : Ws[k * 64 + (n - 64)];
    }
    g_Bf16[i] = __float2half_rn(v);
}

// per-edge weights, padded to multiple of 8 with w=0 sentinels (warp per node)
__global__ void k_wt() {
    int node = (blockIdx.x * blockDim.x + threadIdx.x) >> 5;
    int lane = threadIdx.x & 31;
    if (node >= NN) return;
    int n = g_cnt[node];
    n = (n < CAP) ? n : CAP;
    int bound = (n + 7) & ~7;
    float dd = rsqrtf((float)(g_cnt[node] + 1));
    const int base = node << 7;
    for (int j = lane; j < bound; j += 32) {
        uint2 sw;
        if (j < n) {
            int s = g_src[base + j];
            sw.x = (unsigned)(s << 8);               // byte offset of fp16 row
            sw.y = __float_as_uint(rsqrtf((float)(g_cnt[s] + 1)) * dd);
        } else {
            sw.x = 0;
            sw.y = 0;
        }
        g_sw[base + j] = sw;
    }
}

// ---------------- fp16 tensor-core GEMM, fp16 output -----------------------
// 64x128 CTA tile, 8 warps as 2(m) x 4(n), warp tile 32x32. occ 3 (32 accum).
// FUSE: blocks >= GB run edge scatter. APRE: A fp16 rows -> cp.async path.
static constexpr int ROWB   = 80;                 // padded 32-elem fp16 row
static constexpr int ABYTES = TM * ROWB;          // 5120
static constexpr int BBYTES = 128 * ROWB;         // 10240
static constexpr int STAGE  = ABYTES + BBYTES;    // 15360
static constexpr int GEMM_SMEM = 2 * STAGE;       // 30720

template <int K, int FUSE, int APRE>
__global__ __launch_bounds__(256, 3) void k_tgemm(
    const float* __restrict__ A,
    const __half* __restrict__ Ah,
    const __half* __restrict__ Bf,
    __half* __restrict__ C, const void* __restrict__ eiv)
{
    if (FUSE && blockIdx.x >= GB) {                 // edge-scatter role
        int e = (blockIdx.x - GB) * 256 + threadIdx.x;
        if (e < EE) {
            int s = edge_at(eiv, e);
            int d = edge_at(eiv, (long)EE + e);
            int pos = atomicAdd(&g_cnt[d], 1);
            if (pos < CAP) g_src[(d << 7) + pos] = s;
        }
        return;
    }

    extern __shared__ __align__(256) char smem[];
    constexpr int NCH = K / 32;
    const int tid  = threadIdx.x;
    const int wid  = tid >> 5;
    const int lane = tid & 31;
    const int warp_m = wid & 1;       // 2 row groups of 32
    const int warp_n = wid >> 1;      // 4 col groups of 32
    const uint32_t sb = smem_u32(smem);
    const int rowBase = blockIdx.x * TM;

    const uint32_t a_off = (uint32_t)(((lane & 7) + ((lane >> 3) & 1) * 8) * ROWB
                                      + ((lane >> 4) & 1) * 16);
    const uint32_t b_off = (uint32_t)((((lane >> 4) & 1) * 8 + (lane & 7)) * ROWB
                                      + ((lane >> 3) & 1) * 16);

    float acc[2][4][4];
#pragma unroll
    for (int t = 0; t < 2; t++)
#pragma unroll
        for (int j = 0; j < 4; j++)
#pragma unroll
            for (int v = 0; v < 4; v++) acc[t][j][v] = 0.f;

    const int ar = tid >> 2;          // A fp32 path: 64 rows, 4 thr/row
    const int aq = (tid & 3) * 2;     // quad base; 2 iters -> quads 0..7
    const int br = tid >> 1;          // B: 128 rows, 2 thr/row
    const int bq = (tid & 1) << 1;    // 16B chunk base; 2 iters -> 0..3
    const int apr = tid >> 2;         // A cp path: 64 rows, 4 thr/row
    const int apq = tid & 3;          // 16B chunk 0..3

    auto cpB = [&](int c, int s) {
        uint32_t stb = sb + s * STAGE;
#pragma unroll
        for (int it = 0; it < 2; it++) {
            int q = bq + it;
            uint32_t off = (uint32_t)(br * ROWB + q * 16);
            size_t idx = (size_t)br * K + c * 32 + q * 8;
            cp_async16(stb + ABYTES + off, Bf + idx);
        }
        CP_COMMIT();
    };

    auto cpA = [&](int c, int s) {    // APRE path (fp16 rows in global)
        uint32_t stb = sb + s * STAGE;
        int row = rowBase + apr;
        if (row < NN) {
            uint32_t off = (uint32_t)(apr * ROWB + apq * 16);
            size_t idx = (size_t)row * K + c * 32 + apq * 8;
            cp_async16(stb + off, Ah + idx);
        }
        CP_COMMIT();
    };

    auto ldgA = [&](int c, float4* pa) {
#pragma unroll
        for (int it = 0; it < 2; it++) {
            int q = aq + it;
            int row = rowBase + ar;
            float4 v = make_float4(0.f, 0.f, 0.f, 0.f);
            if (row < NN)
                v = *reinterpret_cast<const float4*>(&A[(size_t)row * K + c * 32 + q * 4]);
            pa[it] = v;
        }
    };

    auto stsA = [&](int s, const float4* pa) {   // fp32 -> fp16
        char* st = smem + s * STAGE;
#pragma unroll
        for (int it = 0; it < 2; it++) {
            int q = aq + it;
            float4 v = pa[it];
            __half2 h01 = __floats2half2_rn(v.x, v.y);
            __half2 h23 = __floats2half2_rn(v.z, v.w);
            uint32_t off = (uint32_t)(ar * ROWB + q * 8);
            *reinterpret_cast<__half2*>(st + off)     = h01;
            *reinterpret_cast<__half2*>(st + off + 4) = h23;
        }
    };

    {   // prologue: chunk 0 -> stage 0
        if (APRE) {
            cpA(0, 0);
            cpB(0, 0);
        } else {
            float4 pa[2];
            ldgA(0, pa);
            cpB(0, 0);
            stsA(0, pa);
        }
        CP_WAIT0();
    }
    __syncthreads();

    for (int c = 0; c < NCH; c++) {
        const int s = c & 1;
        float4 pa[2];
        if (c + 1 < NCH) {
            if (APRE) {
                cpA(c + 1, s ^ 1);
                cpB(c + 1, s ^ 1);
            } else {
                ldgA(c + 1, pa);
                cpB(c + 1, s ^ 1);
            }
        }

        const uint32_t aBase = sb + s * STAGE + (uint32_t)(warp_m * 32) * ROWB;
        const uint32_t bBase = sb + s * STAGE + ABYTES + (uint32_t)(warp_n * 32) * ROWB;

#pragma unroll
        for (int sk = 0; sk < 2; sk++) {
            uint32_t ah[2][4];
#pragma unroll
            for (int t = 0; t < 2; t++) {
                uint32_t ad = aBase + (uint32_t)(t * 16 * ROWB + sk * 32) + a_off;
                LDSM_X4(ah[t][0], ah[t][1], ah[t][2], ah[t][3], ad);
            }
#pragma unroll
            for (int jp = 0; jp < 2; jp++) {
                uint32_t bf[4];
                uint32_t bd = bBase + (uint32_t)(jp * 16 * ROWB + sk * 32) + b_off;
                LDSM_X4(bf[0], bf[1], bf[2], bf[3], bd);
#pragma unroll
                for (int t = 0; t < 2; t++)
#pragma unroll
                    for (int jj = 0; jj < 2; jj++) {
                        int j = jp * 2 + jj, o = jj * 2;
                        MMA_F16(acc[t][j], ah[t], bf[o], bf[o + 1]);
                    }
            }
        }

        if (c + 1 < NCH) {
            if (!APRE) stsA(s ^ 1, pa);
            CP_WAIT0();
        }
        __syncthreads();
    }

    // epilogue: fp16 stores
    const int r0 = rowBase + warp_m * 32 + (lane >> 2);
    const int cb = (lane & 3) * 2;
#pragma unroll
    for (int t = 0; t < 2; t++) {
#pragma unroll
        for (int j = 0; j < 4; j++) {
            int col = warp_n * 32 + j * 8 + cb;
            int ra = r0 + t * 16;
            int rb = ra + 8;
            if (ra < NN)
                *reinterpret_cast<__half2*>(&C[(size_t)ra * 128 + col]) =
                    __floats2half2_rn(acc[t][j][0], acc[t][j][1]);
            if (rb < NN)
                *reinterpret_cast<__half2*>(&C[(size_t)rb * 128 + col]) =
                    __floats2half2_rn(acc[t][j][2], acc[t][j][3]);
        }
    }
}

// ---------------- aggregation: branch-free, 2 edges/warp-iter --------------
// Warp = one node. Lanes 0-15 handle edge j (features fl*8..+8 via uint4),
// lanes 16-31 handle edge j+1; halves combined by shfl_xor(16) at the end.
// Edge list pre-padded (k_wt) to multiple of 2 with w=0 -> no predication.
// MODE 1: h = relu(sum + biasA) -> fp16 rows (next GEMM A input)
// MODE 2: cols 0-63 -> OA + biasA, cols 64-127 -> OB + biasB (fp32 [node][64])
template <int MODE>
__global__ __launch_bounds__(128) void k_agg(
    const __half* __restrict__ G,   // fp16 table rows (256B each)
    const float* __restrict__ biasA, const float* __restrict__ biasB,
    float* __restrict__ OA, float* __restrict__ OB,
    __half* __restrict__ Hh)
{
    int node = (blockIdx.x * blockDim.x + threadIdx.x) >> 5;
    int lane = threadIdx.x & 31;
    if (node >= NN) return;
    int nraw = g_cnt[node];
    int n = (nraw < CAP) ? nraw : CAP;
    int bound = (n + 7) & ~7;
    const int base = node << 7;
    const int half = lane >> 4;
    const int fl   = lane & 15;
    const uint32_t flo = (uint32_t)(fl * 16);
    const char* Gc = (const char*)G;
    float dd = rsqrtf((float)(nraw + 1));

    float acc[8];
    {   // self loop term (half 0 only; half 1 contributes 0)
        uint4 r = *reinterpret_cast<const uint4*>(Gc + ((size_t)node << 8) + flo);
        const __half2* h = reinterpret_cast<const __half2*>(&r);
        float wself = half ? 0.f : dd * dd;
#pragma unroll
        for (int q = 0; q < 4; q++) {
            float2 f = __half22float2(h[q]);
            acc[q * 2]     = wself * f.x;
            acc[q * 2 + 1] = wself * f.y;
        }
    }

    const uint2* swp = &g_sw[base + half];
#pragma unroll 4
    for (int j = 0; j < bound; j += 2) {
        uint2 sw = swp[j];                       // {row byte offset, w}
        float w = __uint_as_float(sw.y);
        uint4 m = *reinterpret_cast<const uint4*>(Gc + sw.x + flo);
        const __half2* h = reinterpret_cast<const __half2*>(&m);
#pragma unroll
        for (int q = 0; q < 4; q++) {
            float2 f = __half22float2(h[q]);
            acc[q * 2]     = fmaf(w, f.x, acc[q * 2]);
            acc[q * 2 + 1] = fmaf(w, f.y, acc[q * 2 + 1]);
        }
    }

    // combine halves
#pragma unroll
    for (int q = 0; q < 8; q++)
        acc[q] += __shfl_xor_sync(0xffffffffu, acc[q], 16);

    if (half == 0) {
        if (MODE == 1) {
            float4 b0 = reinterpret_cast<const float4*>(biasA)[fl * 2];
            float4 b1 = reinterpret_cast<const float4*>(biasA)[fl * 2 + 1];
            float r0 = fmaxf(acc[0] + b0.x, 0.f);
            float r1 = fmaxf(acc[1] + b0.y, 0.f);
            float r2 = fmaxf(acc[2] + b0.z, 0.f);
            float r3 = fmaxf(acc[3] + b0.w, 0.f);
            float r4 = fmaxf(acc[4] + b1.x, 0.f);
            float r5 = fmaxf(acc[5] + b1.y, 0.f);
            float r6 = fmaxf(acc[6] + b1.z, 0.f);
            float r7 = fmaxf(acc[7] + b1.w, 0.f);
            __half2 h0 = __floats2half2_rn(r0, r1);
            __half2 h1 = __floats2half2_rn(r2, r3);
            __half2 h2 = __floats2half2_rn(r4, r5);
            __half2 h3 = __floats2half2_rn(r6, r7);
            uint4 hv;
            hv.x = *reinterpret_cast<uint32_t*>(&h0);
            hv.y = *reinterpret_cast<uint32_t*>(&h1);
            hv.z = *reinterpret_cast<uint32_t*>(&h2);
            hv.w = *reinterpret_cast<uint32_t*>(&h3);
            *reinterpret_cast<uint4*>(Hh + (size_t)node * 128 + fl * 8) = hv;
        } else {
            float*       O    = (fl < 8) ? OA : OB;
            const float* bias = (fl < 8) ? biasA : biasB;
            int f = (fl & 7) * 8;
            float4 b0 = *reinterpret_cast<const float4*>(&bias[f]);
            float4 b1 = *reinterpret_cast<const float4*>(&bias[f + 4]);
            float4 v0 = make_float4(acc[0] + b0.x, acc[1] + b0.y,
                                    acc[2] + b0.z, acc[3] + b0.w);
            float4 v1 = make_float4(acc[4] + b1.x, acc[5] + b1.y,
                                    acc[6] + b1.z, acc[7] + b1.w);
            *reinterpret_cast<float4*>(&O[(size_t)node * 64 + f])     = v0;
            *reinterpret_cast<float4*>(&O[(size_t)node * 64 + f + 4]) = v1;
        }
    }
}

// ---------------- launch ----------------------------------------------------
extern "C" void kernel_launch(void* const* d_in, const int* in_sizes, int n_in,
                              void* d_out, int out_size) {
    const float* x  = (const float*)d_in[0];
    const void*  ei = d_in[1];
    const float* W1 = (const float*)d_in[2];
    const float* b1 = (const float*)d_in[3];
    const float* W2 = (const float*)d_in[4];
    const float* b2 = (const float*)d_in[5];
    const float* Wm = (const float*)d_in[6];
    const float* bm = (const float*)d_in[7];
    const float* Ws = (const float*)d_in[8];
    const float* bs = (const float*)d_in[9];
    float* outM = (float*)d_out;
    float* outS = outM + (long)NN * ZD;

    float*  pA  = nullptr;
    __half* pH  = nullptr;
    __half* pBf = nullptr;
    cudaGetSymbolAddress((void**)&pA,  g_bufA);
    cudaGetSymbolAddress((void**)&pH,  g_H16);
    cudaGetSymbolAddress((void**)&pBf, g_Bf16);
    __half* pAh = (__half*)pA;                       // alias g_bufA

    cudaFuncSetAttribute(k_tgemm<512, 1, 0>, cudaFuncAttributeMaxDynamicSharedMemorySize, GEMM_SMEM);
    cudaFuncSetAttribute(k_tgemm<128, 0, 1>, cudaFuncAttributeMaxDynamicSharedMemorySize, GEMM_SMEM);

    const int T = 256;
    const int ab = (NN * 32 + 127) / 128;      // agg blocks (128 thr)
    const int wb = (NN * 32 + T - 1) / T;      // k_wt blocks

    // init: zero counts + dtype detect + all weight fp16 (1 launch)
    k_init<<<384, T>>>((const int*)ei, W1, W2, Wm, Ws);

    // GEMM1 (single-fp16 A) fused with edge scatter (tail absorption)
    k_tgemm<512, 1, 0><<<GB + EB, T, GEMM_SMEM>>>(x, nullptr, pBf, pH, ei);
    k_wt<<<wb, T>>>();
    k_agg<1><<<ab, 128>>>(pH, b1, nullptr, nullptr, nullptr, pAh);
    // layer 2 (single-fp16 A via cp.async)
    k_tgemm<128, 0, 1><<<GB, T, GEMM_SMEM>>>(nullptr, pAh, pBf + 65536, pH, nullptr);
    k_agg<1><<<ab, 128>>>(pH, b2, nullptr, nullptr, nullptr, pAh);
    // heads (single-fp16 A)
    k_tgemm<128, 0, 1><<<GB, T, GEMM_SMEM>>>(nullptr, pAh, pBf + 81920, pH, nullptr);
    k_agg<2><<<ab, 128>>>(pH, bm, bs, outM, outS, nullptr);
}